// round 16
// baseline (speedup 1.0000x reference)
#include <cuda_runtime.h>
#include <cuda_bf16.h>
#include <cstdint>

#define BB      20000
#define NN      20
#define NODE_D  172
#define EDGE_D  172
#define TIME_D  100
#define QD      272          // NODE_D + TIME_D
#define KD      444          // NODE_D + EDGE_D + TIME_D
#define NH      2
#define HD      136
#define QT      (NH*KD)      // 888
#define ATTN_SCALE 0.08574929257125442f   // 136^-0.5
#define LN_EPS  1e-5f

// GEMM geometry (K-chunk = 32 bf16)
#define KPAD1   288          // GEMM1 K (272 -> 9 chunks; last chunk half-real)
#define NPAD1   896          // GEMM1 N (888 -> 7 tiles of 128)
#define KPAD2   896          // GEMM2 K (888 -> 28 chunks)
#define NPAD2   288          // GEMM2 N (272 -> 3 tiles of 96)
#define NCHUNK1 9
#define NCHUNK2 28
#define RSTR    40           // smem row stride in bf16 (80 B)

// prelude partition
#define NB_PREP ((BB * (KPAD1 / 4) + 255) / 256)     // 5625
#define NB_FM   ((NPAD1 * KPAD1 + 255) / 256)        // 1008
#define NB_RV   ((NPAD2 * KPAD2 + 255) / 256)        // 1008

#define ATH     384          // attention threads (12 warps)

// ---------------- scratch -----------------------------------------------------
__device__ __align__(16) __nv_bfloat16 g_qin_hi[(size_t)BB * KPAD1];
__device__ __align__(16) __nv_bfloat16 g_qin_lo[(size_t)BB * KPAD1];
__device__ __align__(16) __nv_bfloat16 g_Mhi[NPAD1 * KPAD1];
__device__ __align__(16) __nv_bfloat16 g_Mlo[NPAD1 * KPAD1];
__device__ __align__(16) __nv_bfloat16 g_Rvhi[NPAD2 * KPAD2];
__device__ __align__(16) __nv_bfloat16 g_Rvlo[NPAD2 * KPAD2];
__device__ __align__(16) float         g_qt[(size_t)BB * NPAD1];
__device__ __align__(16) __nv_bfloat16 g_cxh[(size_t)BB * KPAD2];
__device__ __align__(16) __nv_bfloat16 g_cxl[(size_t)BB * KPAD2];
__device__ __align__(16) float         g_x[(size_t)BB * QD];

// ---------------- helpers -----------------------------------------------------
__device__ __forceinline__ uint32_t smem_u32(const void* p) {
    uint32_t a;
    asm("{ .reg .u64 t; cvta.to.shared.u64 t, %1; cvt.u32.u64 %0, t; }" : "=r"(a) : "l"(p));
    return a;
}
__device__ __forceinline__ void cp16(uint32_t dst, const void* src, bool v) {
    int sz = v ? 16 : 0;
    asm volatile("cp.async.cg.shared.global [%0], [%1], 16, %2;"
                 :: "r"(dst), "l"(src), "r"(sz));
}
#define CP_COMMIT() asm volatile("cp.async.commit_group;" ::: "memory")
#define CP_WAIT(n)  asm volatile("cp.async.wait_group %0;" :: "n"(n) : "memory")

#define LDM_X4(r, a) \
    asm volatile("ldmatrix.sync.aligned.m8n8.x4.shared.b16 {%0,%1,%2,%3}, [%4];" \
                 : "=r"((r)[0]), "=r"((r)[1]), "=r"((r)[2]), "=r"((r)[3]) : "r"(a))

__device__ __forceinline__ void mma_bf16(float* c, const uint32_t a[4],
                                         uint32_t b0, uint32_t b1) {
    asm volatile(
        "mma.sync.aligned.m16n8k16.row.col.f32.bf16.bf16.f32 "
        "{%0,%1,%2,%3}, {%4,%5,%6,%7}, {%8,%9}, {%0,%1,%2,%3};"
        : "+f"(c[0]), "+f"(c[1]), "+f"(c[2]), "+f"(c[3])
        : "r"(a[0]), "r"(a[1]), "r"(a[2]), "r"(a[3]), "r"(b0), "r"(b1));
}

__device__ __forceinline__ void split_bf16(float x, __nv_bfloat16& h, __nv_bfloat16& l) {
    h = __float2bfloat16(x);
    l = __float2bfloat16(x - __bfloat162float(h));
}

// ---------------- fused prelude: prep_qin | fold_M | fold_Rv ------------------
__global__ void k_prelude(const float* __restrict__ nodef, const float* __restrict__ ntime,
                          const float* __restrict__ Wq, const float* __restrict__ Wk,
                          const float* __restrict__ Wr, const float* __restrict__ Wv)
{
    const int bid = blockIdx.x;
    if (bid < NB_PREP) {
        int i = bid * 256 + threadIdx.x;
        if (i >= BB * (KPAD1 / 4)) return;
        int r = i / (KPAD1 / 4), c = (i % (KPAD1 / 4)) * 4;
        float4 x = make_float4(0.f, 0.f, 0.f, 0.f);
        if (c < NODE_D)   x = *(const float4*)(nodef + (size_t)r * NODE_D + c);
        else if (c < QD)  x = *(const float4*)(ntime + (size_t)r * TIME_D + (c - NODE_D));
        uint64_t ph, pl;
        __nv_bfloat16* hh = (__nv_bfloat16*)&ph;
        __nv_bfloat16* ll = (__nv_bfloat16*)&pl;
        split_bf16(x.x, hh[0], ll[0]);
        split_bf16(x.y, hh[1], ll[1]);
        split_bf16(x.z, hh[2], ll[2]);
        split_bf16(x.w, hh[3], ll[3]);
        *(uint64_t*)(g_qin_hi + (size_t)i * 4) = ph;
        *(uint64_t*)(g_qin_lo + (size_t)i * 4) = pl;
    } else if (bid < NB_PREP + NB_FM) {
        int tid = (bid - NB_PREP) * 256 + threadIdx.x;
        if (tid >= NPAD1 * KPAD1) return;
        int c = tid % KPAD1;
        int o = tid / KPAD1;
        float acc = 0.f;
        if (o < QT && c < QD) {
            int h = o / KD, j = o % KD;
            const float* wk = Wk + (size_t)(h * HD) * KD + j;
            const float* wq = Wq + (size_t)(h * HD) * QD + c;
#pragma unroll 8
            for (int d = 0; d < HD; ++d)
                acc += wk[(size_t)d * KD] * wq[(size_t)d * QD];
        }
        __nv_bfloat16 h16, l16; split_bf16(acc, h16, l16);
        g_Mhi[tid] = h16; g_Mlo[tid] = l16;
    } else {
        int tid = (bid - NB_PREP - NB_FM) * 256 + threadIdx.x;
        if (tid >= NPAD2 * KPAD2) return;
        int p = tid % KPAD2;
        int o = tid / KPAD2;
        float acc = 0.f;
        if (o < QD && p < QT) {
            int h = p / KD, j = p % KD;
            const float* wr = Wr + (size_t)o * QD + h * HD;
            const float* wv = Wv + (size_t)(h * HD) * KD + j;
#pragma unroll 8
            for (int d = 0; d < HD; ++d)
                acc += wr[d] * wv[(size_t)d * KD];
        }
        __nv_bfloat16 h16, l16; split_bf16(acc, h16, l16);
        g_Rvhi[tid] = h16; g_Rvlo[tid] = l16;
    }
}

// ---------------- bf16x3 HMMA GEMM --------------------------------------------
// MINB: __launch_bounds__ min-blocks hint (3 for G2 -> <=85 regs -> 3 CTAs/SM).
template<int BN, int NCH, int KP, int OSTR, bool FUSE, int WHICH, int STAGES, bool HALFLAST, int MINB>
__global__ __launch_bounds__(256, MINB)
void k_gemm_mma(const float* __restrict__ nodef, const float* __restrict__ ntime,
                const float* __restrict__ br)
{
    const __nv_bfloat16* __restrict__ Ah = (WHICH == 1) ? g_qin_hi : g_cxh;
    const __nv_bfloat16* __restrict__ Al = (WHICH == 1) ? g_qin_lo : g_cxl;
    const __nv_bfloat16* __restrict__ Bh = (WHICH == 1) ? g_Mhi : g_Rvhi;
    const __nv_bfloat16* __restrict__ Bl = (WHICH == 1) ? g_Mlo : g_Rvlo;
    float* __restrict__ outp             = (WHICH == 1) ? g_qt : g_x;

    constexpr int WN   = BN / 2;
    constexpr int WNS  = WN / 8;
    constexpr int NG   = WN / 16;
    constexpr int OFF_AL = 128 * 2 * RSTR;
    constexpr int OFF_BH = 2 * OFF_AL;
    constexpr int OFF_BL = OFF_BH + BN * 2 * RSTR;
    constexpr int STRIDE = OFF_BL + BN * 2 * RSTR;

    extern __shared__ char sm[];
    const uint32_t S = smem_u32(sm);
    const int t = threadIdx.x, lane = t & 31, wid = t >> 5;
    const int warpM = wid & 3, warpN = wid >> 2;
    const int bm = blockIdx.x, bn = blockIdx.y;

    float acc[2][WNS][4];
#pragma unroll
    for (int i = 0; i < 2; i++)
#pragma unroll
        for (int j = 0; j < WNS; j++)
#pragma unroll
            for (int q = 0; q < 4; q++) acc[i][j][q] = 0.f;

    auto load_chunk = [&](int c, int b) {
        const uint32_t base = S + b * STRIDE;
        for (int i = t; i < 512; i += 256) {
            int row = i >> 2, seg = i & 3;
            int gr = bm * 128 + row;
            bool v = gr < BB;
            int grc = v ? gr : (BB - 1);
            size_t off = (size_t)grc * KP + c * 32 + seg * 8;
            cp16(base + row * 80 + seg * 16, Ah + off, v);
            cp16(base + OFF_AL + row * 80 + seg * 16, Al + off, v);
        }
        for (int i = t; i < BN * 4; i += 256) {
            int row = i >> 2, seg = i & 3;
            size_t off = (size_t)(bn * BN + row) * KP + c * 32 + seg * 8;
            cp16(base + OFF_BH + row * 80 + seg * 16, Bh + off, true);
            cp16(base + OFF_BL + row * 80 + seg * 16, Bl + off, true);
        }
    };

    // R12-style full-chunk compute: static unrolled kk loop inside one lambda
    auto compute_chunk = [&](int bufIdx) {
        const uint32_t base = S + bufIdx * STRIDE;
        const uint32_t lrow = lane & 15;
        const uint32_t lcol = (lane >> 4) * 16;
#pragma unroll
        for (int kk = 0; kk < 2; kk++) {
            const uint32_t kb = kk * 32 + lcol;
            uint32_t a_hi[2][4], a_lo[2][4];
#pragma unroll
            for (int ms = 0; ms < 2; ms++) {
                uint32_t r0 = (warpM * 32 + ms * 16 + lrow) * 80 + kb;
                LDM_X4(a_hi[ms], base + r0);
                LDM_X4(a_lo[ms], base + OFF_AL + r0);
            }
#pragma unroll
            for (int ng = 0; ng < NG; ng++) {
                uint32_t bh[4], bl[4];
                uint32_t r0 = (warpN * WN + ng * 16 + lrow) * 80 + kb;
                LDM_X4(bh, base + OFF_BH + r0);
                LDM_X4(bl, base + OFF_BL + r0);
#pragma unroll
                for (int ms = 0; ms < 2; ms++) {
                    mma_bf16(acc[ms][2*ng],   a_hi[ms], bh[0], bh[2]);
                    mma_bf16(acc[ms][2*ng+1], a_hi[ms], bh[1], bh[3]);
                }
#pragma unroll
                for (int ms = 0; ms < 2; ms++) {
                    mma_bf16(acc[ms][2*ng],   a_hi[ms], bl[0], bl[2]);
                    mma_bf16(acc[ms][2*ng+1], a_hi[ms], bl[1], bl[3]);
                }
#pragma unroll
                for (int ms = 0; ms < 2; ms++) {
                    mma_bf16(acc[ms][2*ng],   a_lo[ms], bh[0], bh[2]);
                    mma_bf16(acc[ms][2*ng+1], a_lo[ms], bh[1], bh[3]);
                }
            }
        }
    };

    // half-chunk compute (kk=0 only) — used ONLY for G1's peeled final chunk
    auto compute_half0 = [&](int bufIdx) {
        const uint32_t base = S + bufIdx * STRIDE;
        const uint32_t lrow = lane & 15;
        const uint32_t lcol = (lane >> 4) * 16;
        const uint32_t kb = lcol;
        uint32_t a_hi[2][4], a_lo[2][4];
#pragma unroll
        for (int ms = 0; ms < 2; ms++) {
            uint32_t r0 = (warpM * 32 + ms * 16 + lrow) * 80 + kb;
            LDM_X4(a_hi[ms], base + r0);
            LDM_X4(a_lo[ms], base + OFF_AL + r0);
        }
#pragma unroll
        for (int ng = 0; ng < NG; ng++) {
            uint32_t bh[4], bl[4];
            uint32_t r0 = (warpN * WN + ng * 16 + lrow) * 80 + kb;
            LDM_X4(bh, base + OFF_BH + r0);
            LDM_X4(bl, base + OFF_BL + r0);
#pragma unroll
            for (int ms = 0; ms < 2; ms++) {
                mma_bf16(acc[ms][2*ng],   a_hi[ms], bh[0], bh[2]);
                mma_bf16(acc[ms][2*ng+1], a_hi[ms], bh[1], bh[3]);
            }
#pragma unroll
            for (int ms = 0; ms < 2; ms++) {
                mma_bf16(acc[ms][2*ng],   a_hi[ms], bl[0], bl[2]);
                mma_bf16(acc[ms][2*ng+1], a_hi[ms], bl[1], bl[3]);
            }
#pragma unroll
            for (int ms = 0; ms < 2; ms++) {
                mma_bf16(acc[ms][2*ng],   a_lo[ms], bh[0], bh[2]);
                mma_bf16(acc[ms][2*ng+1], a_lo[ms], bh[1], bh[3]);
            }
        }
    };

    if (STAGES == 2) {
        load_chunk(0, 0); CP_COMMIT();
        for (int c = 0; c < NCH - 1; c++) {
            load_chunk(c + 1, (c + 1) & 1); CP_COMMIT(); CP_WAIT(1);
            __syncthreads();
            compute_chunk(c & 1);
            __syncthreads();
        }
        CP_WAIT(0);
        __syncthreads();
        if (HALFLAST) compute_half0((NCH - 1) & 1);
        else          compute_chunk((NCH - 1) & 1);
    } else {
        load_chunk(0, 0); CP_COMMIT();
        load_chunk(1, 1); CP_COMMIT();
        int bufc = 0;
        for (int c = 0; c < NCH; c++) {
            CP_WAIT(1);
            __syncthreads();
            if (c + 2 < NCH) {
                int b2 = bufc + 2; if (b2 >= 3) b2 -= 3;
                load_chunk(c + 2, b2);
            }
            CP_COMMIT();
            compute_chunk(bufc);
            bufc = (bufc == 2) ? 0 : bufc + 1;
        }
    }

    const int g = lane >> 2, tq = lane & 3;
#pragma unroll
    for (int ms = 0; ms < 2; ms++) {
#pragma unroll
        for (int ns = 0; ns < WNS; ns++) {
            int row = bm * 128 + warpM * 32 + ms * 16 + g;
            int col = bn * BN + warpN * WN + ns * 8 + tq * 2;
#pragma unroll
            for (int half = 0; half < 2; half++) {
                int r = row + half * 8;
                if (r >= BB) continue;
                float v0 = acc[ms][ns][half * 2 + 0];
                float v1 = acc[ms][ns][half * 2 + 1];
                if (FUSE) {
                    if (col >= QD) continue;
                    float2 res;
                    if (col < NODE_D) res = *(const float2*)(nodef + (size_t)r * NODE_D + col);
                    else              res = *(const float2*)(ntime + (size_t)r * TIME_D + (col - NODE_D));
                    float2 bb = *(const float2*)(br + col);
                    v0 += bb.x + res.x;
                    v1 += bb.y + res.y;
                }
                *(float2*)(outp + (size_t)r * OSTR + col) = make_float2(v0, v1);
            }
        }
    }
}

// ---------------- K2: mask-compacted streaming attention (384 threads) --------
__global__ __launch_bounds__(ATH)
void k_attn(const float* __restrict__ nbr_node, const float* __restrict__ nbr_time,
            const float* __restrict__ nbr_edge, const int* __restrict__ masks,
            float* __restrict__ out)
{
    __shared__ __align__(16) float kv[NN * KD];   // compact slots
    __shared__ __align__(16) float qts[QT];
    __shared__ float sc[NH * NN];                 // scores/attn by neighbor idx
    __shared__ float aw[NH * NN];                 // attn by compact slot

    const int b = blockIdx.x;
    const int t = threadIdx.x;
    const int w = t >> 5, lane = t & 31;
    const uint32_t kvS  = smem_u32(kv);
    const uint32_t qtsS = smem_u32(qts);

    int mv = (lane < NN) ? (masks[(size_t)b * NN + lane] != 0) : 0;
    uint32_t mb = __ballot_sync(0xffffffffu, mv) & 0xFFFFFu;
    const bool allmask = (mb == 0);
    if (allmask) mb = 0xFFFFFu;
    const int nact = __popc(mb);

    for (int i = t; i < QT / 4; i += ATH)
        cp16(qtsS + i * 16, g_qt + (size_t)b * NPAD1 + i * 4, true);
    for (int i = t; i < nact * (NODE_D / 4); i += ATH) {
        int s = i / (NODE_D / 4), j4 = i % (NODE_D / 4);
        int n = __fns(mb, 0, s + 1);
        cp16(kvS + (s * KD + j4 * 4) * 4,
             nbr_node + ((size_t)b * NN + n) * NODE_D + j4 * 4, true);
    }
    for (int i = t; i < nact * (EDGE_D / 4); i += ATH) {
        int s = i / (EDGE_D / 4), j4 = i % (EDGE_D / 4);
        int n = __fns(mb, 0, s + 1);
        cp16(kvS + (s * KD + NODE_D + j4 * 4) * 4,
             nbr_edge + ((size_t)b * NN + n) * EDGE_D + j4 * 4, true);
    }
    for (int i = t; i < nact * (TIME_D / 4); i += ATH) {
        int s = i / (TIME_D / 4), j4 = i % (TIME_D / 4);
        int n = __fns(mb, 0, s + 1);
        cp16(kvS + (s * KD + NODE_D + EDGE_D + j4 * 4) * 4,
             nbr_time + ((size_t)b * NN + n) * TIME_D + j4 * 4, true);
    }
    if (t < NH * NN) sc[t] = -1e10f;
    CP_COMMIT();
    CP_WAIT(0);
    __syncthreads();

    // ---- scores: warp w -> slots w and w+12, both heads ----
#pragma unroll
    for (int rep = 0; rep < 2; rep++) {
        int s = w + rep * 12;
        if (s < nact) {
            int n = __fns(mb, 0, s + 1);
            float a0 = 0.f, a1 = 0.f;
            for (int j = lane; j < KD; j += 32) {
                float kvv = kv[s * KD + j];
                a0 += qts[j] * kvv;
                a1 += qts[KD + j] * kvv;
            }
#pragma unroll
            for (int o = 16; o; o >>= 1) {
                a0 += __shfl_xor_sync(0xffffffffu, a0, o);
                a1 += __shfl_xor_sync(0xffffffffu, a1, o);
            }
            if (lane == 0) {
                sc[n]      = allmask ? 0.f : a0 * ATTN_SCALE;
                sc[NN + n] = allmask ? 0.f : a1 * ATTN_SCALE;
            }
        }
    }
    __syncthreads();

    // ---- softmax: warp h handles head h; write attn output + slot weights ----
    if (w < NH) {
        const int h = w;
        float x = (lane < NN) ? sc[h * NN + lane] : -INFINITY;
        float m = x;
#pragma unroll
        for (int o = 16; o; o >>= 1) m = fmaxf(m, __shfl_xor_sync(0xffffffffu, m, o));
        float e = (lane < NN) ? __expf(x - m) : 0.f;
        float ssum = e;
#pragma unroll
        for (int o = 16; o; o >>= 1) ssum += __shfl_xor_sync(0xffffffffu, ssum, o);
        float a = e / ssum;
        if (lane < NN) {
            out[(size_t)BB * QD + ((size_t)b * NH + h) * NN + lane] = a;
            if ((mb >> lane) & 1u) {
                int s = __popc(mb & ((1u << lane) - 1u));
                aw[h * NN + s] = a;
            }
        }
    }
    __syncthreads();

    // ---- ctx: sum over ACTIVE slots, both heads per element ----
    for (int j = t; j < KD; j += ATH) {
        float c0 = 0.f, c1 = 0.f;
        for (int s = 0; s < nact; ++s) {
            float kvv = kv[s * KD + j];
            c0 += aw[s] * kvv;
            c1 += aw[NN + s] * kvv;
        }
        __nv_bfloat16 h0 = __float2bfloat16(c0);
        __nv_bfloat16 h1 = __float2bfloat16(c1);
        size_t base = (size_t)b * KPAD2;
        g_cxh[base + j]      = h0;
        g_cxl[base + j]      = __float2bfloat16(c0 - __bfloat162float(h0));
        g_cxh[base + KD + j] = h1;
        g_cxl[base + KD + j] = __float2bfloat16(c1 - __bfloat162float(h1));
    }
    if (t < KPAD2 - QT) {
        g_cxh[(size_t)b * KPAD2 + QT + t] = __float2bfloat16(0.f);
        g_cxl[(size_t)b * KPAD2 + QT + t] = __float2bfloat16(0.f);
    }
}

// ---------------- LayerNorm, one warp per row, float4-vectorized ---------------
__global__ __launch_bounds__(256)
void k_ln(const float* __restrict__ gamma, const float* __restrict__ beta,
          float* __restrict__ out)
{
    int gw   = (blockIdx.x * blockDim.x + threadIdx.x) >> 5;
    int lane = threadIdx.x & 31;
    if (gw >= BB) return;
    const float4* x4 = (const float4*)(g_x + (size_t)gw * QD);
    float s = 0.f, s2 = 0.f;
    for (int j = lane; j < QD / 4; j += 32) {
        float4 v = x4[j];
        s  += v.x + v.y + v.z + v.w;
        s2 += v.x * v.x + v.y * v.y + v.z * v.z + v.w * v.w;
    }
#pragma unroll
    for (int o = 16; o; o >>= 1) {
        s  += __shfl_xor_sync(0xffffffffu, s,  o);
        s2 += __shfl_xor_sync(0xffffffffu, s2, o);
    }
    float mu   = s * (1.f / QD);
    float var  = s2 * (1.f / QD) - mu * mu;
    float rstd = rsqrtf(var + LN_EPS);
    float4* o4 = (float4*)(out + (size_t)gw * QD);
    const float4* g4 = (const float4*)gamma;
    const float4* b4 = (const float4*)beta;
    for (int j = lane; j < QD / 4; j += 32) {
        float4 v = x4[j], gg = g4[j], bb = b4[j];
        v.x = (v.x - mu) * rstd * gg.x + bb.x;
        v.y = (v.y - mu) * rstd * gg.y + bb.y;
        v.z = (v.z - mu) * rstd * gg.z + bb.z;
        v.w = (v.w - mu) * rstd * gg.w + bb.w;
        o4[j] = v;
    }
}

// ---------------- launch ------------------------------------------------------
#define SMEM1 (2 * (4 * 128 * 2 * RSTR))                       // 81920 (2-stage, BN=128)
#define SMEM2 (2 * (2 * 128 * 2 * RSTR + 2 * 96 * 2 * RSTR))   // 71680 (2-stage, BN=96)

extern "C" void kernel_launch(void* const* d_in, const int* in_sizes, int n_in,
                              void* d_out, int out_size)
{
    const float* nodef    = (const float*)d_in[0];
    const float* ntime    = (const float*)d_in[1];
    const float* nbr_node = (const float*)d_in[2];
    const float* nbr_time = (const float*)d_in[3];
    const float* nbr_edge = (const float*)d_in[4];
    const int*   masks    = (const int*)  d_in[5];
    const float* Wq       = (const float*)d_in[6];
    const float* Wk       = (const float*)d_in[7];
    const float* Wv       = (const float*)d_in[8];
    const float* Wr       = (const float*)d_in[9];
    const float* br       = (const float*)d_in[10];
    const float* gamma    = (const float*)d_in[11];
    const float* beta     = (const float*)d_in[12];
    float* out = (float*)d_out;

    auto g1 = k_gemm_mma<128, NCHUNK1, KPAD1, NPAD1, false, 1, 2, true,  2>;
    auto g2 = k_gemm_mma<96,  NCHUNK2, KPAD2, QD,    true,  2, 2, false, 3>;
    cudaFuncSetAttribute(g1, cudaFuncAttributeMaxDynamicSharedMemorySize, SMEM1);
    cudaFuncSetAttribute(g2, cudaFuncAttributeMaxDynamicSharedMemorySize, SMEM2);

    k_prelude<<<NB_PREP + NB_FM + NB_RV, 256>>>(nodef, ntime, Wq, Wk, Wr, Wv);

    dim3 grid1((BB + 127) / 128, NPAD1 / 128);
    g1<<<grid1, 256, SMEM1>>>(nodef, ntime, br);

    k_attn<<<BB, ATH>>>(nbr_node, nbr_time, nbr_edge, masks, out);

    dim3 grid2((BB + 127) / 128, NPAD2 / 96);
    g2<<<grid2, 256, SMEM2>>>(nodef, ntime, br);

    k_ln<<<(BB * 32 + 255) / 256, 256>>>(gamma, beta, out);
}

// round 17
// speedup vs baseline: 1.0353x; 1.0353x over previous
#include <cuda_runtime.h>
#include <cuda_bf16.h>
#include <cstdint>

#define BB      20000
#define NN      20
#define NODE_D  172
#define EDGE_D  172
#define TIME_D  100
#define QD      272          // NODE_D + TIME_D
#define KD      444          // NODE_D + EDGE_D + TIME_D
#define NH      2
#define HD      136
#define QT      (NH*KD)      // 888
#define ATTN_SCALE 0.08574929257125442f   // 136^-0.5
#define LN_EPS  1e-5f

// GEMM geometry (K-chunk = 32 bf16)
#define KPAD1   288          // GEMM1 K (272 -> 9 chunks; last chunk half-real)
#define NPAD1   896          // GEMM1 N (888 -> 7 tiles of 128)
#define KPAD2   896          // GEMM2 K (888 -> 28 chunks)
#define NPAD2   288          // GEMM2 N (272 -> 3 tiles of 96)
#define NCHUNK1 9
#define NCHUNK2 28
#define RSTR    40           // smem row stride in bf16 (80 B)

// prelude partition
#define NB_PREP ((BB * (KPAD1 / 4) + 255) / 256)     // 5625
#define NB_FM   ((NPAD1 * KPAD1 + 255) / 256)        // 1008
#define NB_RV   ((NPAD2 * KPAD2 + 255) / 256)        // 1008

#define ATH     384          // attention threads (12 warps)

// attn/G2 overlap split: 79 bm tiles = 10112 rows
#define TSPLIT  79
#define RSPLIT  (TSPLIT * 128)
#define NTILES2 157          // total G2 bm tiles

// ---------------- scratch -----------------------------------------------------
__device__ __align__(16) __nv_bfloat16 g_qin_hi[(size_t)BB * KPAD1];
__device__ __align__(16) __nv_bfloat16 g_qin_lo[(size_t)BB * KPAD1];
__device__ __align__(16) __nv_bfloat16 g_Mhi[NPAD1 * KPAD1];
__device__ __align__(16) __nv_bfloat16 g_Mlo[NPAD1 * KPAD1];
__device__ __align__(16) __nv_bfloat16 g_Rvhi[NPAD2 * KPAD2];
__device__ __align__(16) __nv_bfloat16 g_Rvlo[NPAD2 * KPAD2];
__device__ __align__(16) float         g_qt[(size_t)BB * NPAD1];
__device__ __align__(16) __nv_bfloat16 g_cxh[(size_t)BB * KPAD2];
__device__ __align__(16) __nv_bfloat16 g_cxl[(size_t)BB * KPAD2];
__device__ __align__(16) float         g_x[(size_t)BB * QD];

// ---------------- helpers -----------------------------------------------------
__device__ __forceinline__ uint32_t smem_u32(const void* p) {
    uint32_t a;
    asm("{ .reg .u64 t; cvta.to.shared.u64 t, %1; cvt.u32.u64 %0, t; }" : "=r"(a) : "l"(p));
    return a;
}
__device__ __forceinline__ void cp16(uint32_t dst, const void* src, bool v) {
    int sz = v ? 16 : 0;
    asm volatile("cp.async.cg.shared.global [%0], [%1], 16, %2;"
                 :: "r"(dst), "l"(src), "r"(sz));
}
#define CP_COMMIT() asm volatile("cp.async.commit_group;" ::: "memory")
#define CP_WAIT(n)  asm volatile("cp.async.wait_group %0;" :: "n"(n) : "memory")

#define LDM_X4(r, a) \
    asm volatile("ldmatrix.sync.aligned.m8n8.x4.shared.b16 {%0,%1,%2,%3}, [%4];" \
                 : "=r"((r)[0]), "=r"((r)[1]), "=r"((r)[2]), "=r"((r)[3]) : "r"(a))

__device__ __forceinline__ void mma_bf16(float* c, const uint32_t a[4],
                                         uint32_t b0, uint32_t b1) {
    asm volatile(
        "mma.sync.aligned.m16n8k16.row.col.f32.bf16.bf16.f32 "
        "{%0,%1,%2,%3}, {%4,%5,%6,%7}, {%8,%9}, {%0,%1,%2,%3};"
        : "+f"(c[0]), "+f"(c[1]), "+f"(c[2]), "+f"(c[3])
        : "r"(a[0]), "r"(a[1]), "r"(a[2]), "r"(a[3]), "r"(b0), "r"(b1));
}

__device__ __forceinline__ void split_bf16(float x, __nv_bfloat16& h, __nv_bfloat16& l) {
    h = __float2bfloat16(x);
    l = __float2bfloat16(x - __bfloat162float(h));
}

// ---------------- fused prelude: prep_qin | fold_M | fold_Rv ------------------
__global__ void k_prelude(const float* __restrict__ nodef, const float* __restrict__ ntime,
                          const float* __restrict__ Wq, const float* __restrict__ Wk,
                          const float* __restrict__ Wr, const float* __restrict__ Wv)
{
    const int bid = blockIdx.x;
    if (bid < NB_PREP) {
        int i = bid * 256 + threadIdx.x;
        if (i >= BB * (KPAD1 / 4)) return;
        int r = i / (KPAD1 / 4), c = (i % (KPAD1 / 4)) * 4;
        float4 x = make_float4(0.f, 0.f, 0.f, 0.f);
        if (c < NODE_D)   x = *(const float4*)(nodef + (size_t)r * NODE_D + c);
        else if (c < QD)  x = *(const float4*)(ntime + (size_t)r * TIME_D + (c - NODE_D));
        uint64_t ph, pl;
        __nv_bfloat16* hh = (__nv_bfloat16*)&ph;
        __nv_bfloat16* ll = (__nv_bfloat16*)&pl;
        split_bf16(x.x, hh[0], ll[0]);
        split_bf16(x.y, hh[1], ll[1]);
        split_bf16(x.z, hh[2], ll[2]);
        split_bf16(x.w, hh[3], ll[3]);
        *(uint64_t*)(g_qin_hi + (size_t)i * 4) = ph;
        *(uint64_t*)(g_qin_lo + (size_t)i * 4) = pl;
    } else if (bid < NB_PREP + NB_FM) {
        int tid = (bid - NB_PREP) * 256 + threadIdx.x;
        if (tid >= NPAD1 * KPAD1) return;
        int c = tid % KPAD1;
        int o = tid / KPAD1;
        float acc = 0.f;
        if (o < QT && c < QD) {
            int h = o / KD, j = o % KD;
            const float* wk = Wk + (size_t)(h * HD) * KD + j;
            const float* wq = Wq + (size_t)(h * HD) * QD + c;
#pragma unroll 8
            for (int d = 0; d < HD; ++d)
                acc += wk[(size_t)d * KD] * wq[(size_t)d * QD];
        }
        __nv_bfloat16 h16, l16; split_bf16(acc, h16, l16);
        g_Mhi[tid] = h16; g_Mlo[tid] = l16;
    } else {
        int tid = (bid - NB_PREP - NB_FM) * 256 + threadIdx.x;
        if (tid >= NPAD2 * KPAD2) return;
        int p = tid % KPAD2;
        int o = tid / KPAD2;
        float acc = 0.f;
        if (o < QD && p < QT) {
            int h = p / KD, j = p % KD;
            const float* wr = Wr + (size_t)o * QD + h * HD;
            const float* wv = Wv + (size_t)(h * HD) * KD + j;
#pragma unroll 8
            for (int d = 0; d < HD; ++d)
                acc += wr[d] * wv[(size_t)d * KD];
        }
        __nv_bfloat16 h16, l16; split_bf16(acc, h16, l16);
        g_Rvhi[tid] = h16; g_Rvlo[tid] = l16;
    }
}

// ---------------- bf16x3 HMMA GEMM (row-ranged) --------------------------------
template<int BN, int NCH, int KP, int OSTR, bool FUSE, int WHICH, int STAGES, bool HALFLAST>
__global__ __launch_bounds__(256)
void k_gemm_mma(const float* __restrict__ nodef, const float* __restrict__ ntime,
                const float* __restrict__ br, int rowBeg, int rowEnd)
{
    const __nv_bfloat16* __restrict__ Ah = (WHICH == 1) ? g_qin_hi : g_cxh;
    const __nv_bfloat16* __restrict__ Al = (WHICH == 1) ? g_qin_lo : g_cxl;
    const __nv_bfloat16* __restrict__ Bh = (WHICH == 1) ? g_Mhi : g_Rvhi;
    const __nv_bfloat16* __restrict__ Bl = (WHICH == 1) ? g_Mlo : g_Rvlo;
    float* __restrict__ outp             = (WHICH == 1) ? g_qt : g_x;

    constexpr int WN   = BN / 2;
    constexpr int WNS  = WN / 8;
    constexpr int NG   = WN / 16;
    constexpr int OFF_AL = 128 * 2 * RSTR;
    constexpr int OFF_BH = 2 * OFF_AL;
    constexpr int OFF_BL = OFF_BH + BN * 2 * RSTR;
    constexpr int STRIDE = OFF_BL + BN * 2 * RSTR;

    extern __shared__ char sm[];
    const uint32_t S = smem_u32(sm);
    const int t = threadIdx.x, lane = t & 31, wid = t >> 5;
    const int warpM = wid & 3, warpN = wid >> 2;
    const int bm = blockIdx.x, bn = blockIdx.y;

    float acc[2][WNS][4];
#pragma unroll
    for (int i = 0; i < 2; i++)
#pragma unroll
        for (int j = 0; j < WNS; j++)
#pragma unroll
            for (int q = 0; q < 4; q++) acc[i][j][q] = 0.f;

    auto load_chunk = [&](int c, int b) {
        const uint32_t base = S + b * STRIDE;
        for (int i = t; i < 512; i += 256) {
            int row = i >> 2, seg = i & 3;
            int gr = rowBeg + bm * 128 + row;
            bool v = gr < rowEnd;
            int grc = v ? gr : (rowEnd - 1);
            size_t off = (size_t)grc * KP + c * 32 + seg * 8;
            cp16(base + row * 80 + seg * 16, Ah + off, v);
            cp16(base + OFF_AL + row * 80 + seg * 16, Al + off, v);
        }
        for (int i = t; i < BN * 4; i += 256) {
            int row = i >> 2, seg = i & 3;
            size_t off = (size_t)(bn * BN + row) * KP + c * 32 + seg * 8;
            cp16(base + OFF_BH + row * 80 + seg * 16, Bh + off, true);
            cp16(base + OFF_BL + row * 80 + seg * 16, Bl + off, true);
        }
    };

    auto compute_chunk = [&](int bufIdx) {
        const uint32_t base = S + bufIdx * STRIDE;
        const uint32_t lrow = lane & 15;
        const uint32_t lcol = (lane >> 4) * 16;
#pragma unroll
        for (int kk = 0; kk < 2; kk++) {
            const uint32_t kb = kk * 32 + lcol;
            uint32_t a_hi[2][4], a_lo[2][4];
#pragma unroll
            for (int ms = 0; ms < 2; ms++) {
                uint32_t r0 = (warpM * 32 + ms * 16 + lrow) * 80 + kb;
                LDM_X4(a_hi[ms], base + r0);
                LDM_X4(a_lo[ms], base + OFF_AL + r0);
            }
#pragma unroll
            for (int ng = 0; ng < NG; ng++) {
                uint32_t bh[4], bl[4];
                uint32_t r0 = (warpN * WN + ng * 16 + lrow) * 80 + kb;
                LDM_X4(bh, base + OFF_BH + r0);
                LDM_X4(bl, base + OFF_BL + r0);
#pragma unroll
                for (int ms = 0; ms < 2; ms++) {
                    mma_bf16(acc[ms][2*ng],   a_hi[ms], bh[0], bh[2]);
                    mma_bf16(acc[ms][2*ng+1], a_hi[ms], bh[1], bh[3]);
                }
#pragma unroll
                for (int ms = 0; ms < 2; ms++) {
                    mma_bf16(acc[ms][2*ng],   a_hi[ms], bl[0], bl[2]);
                    mma_bf16(acc[ms][2*ng+1], a_hi[ms], bl[1], bl[3]);
                }
#pragma unroll
                for (int ms = 0; ms < 2; ms++) {
                    mma_bf16(acc[ms][2*ng],   a_lo[ms], bh[0], bh[2]);
                    mma_bf16(acc[ms][2*ng+1], a_lo[ms], bh[1], bh[3]);
                }
            }
        }
    };

    auto compute_half0 = [&](int bufIdx) {
        const uint32_t base = S + bufIdx * STRIDE;
        const uint32_t lrow = lane & 15;
        const uint32_t lcol = (lane >> 4) * 16;
        const uint32_t kb = lcol;
        uint32_t a_hi[2][4], a_lo[2][4];
#pragma unroll
        for (int ms = 0; ms < 2; ms++) {
            uint32_t r0 = (warpM * 32 + ms * 16 + lrow) * 80 + kb;
            LDM_X4(a_hi[ms], base + r0);
            LDM_X4(a_lo[ms], base + OFF_AL + r0);
        }
#pragma unroll
        for (int ng = 0; ng < NG; ng++) {
            uint32_t bh[4], bl[4];
            uint32_t r0 = (warpN * WN + ng * 16 + lrow) * 80 + kb;
            LDM_X4(bh, base + OFF_BH + r0);
            LDM_X4(bl, base + OFF_BL + r0);
#pragma unroll
            for (int ms = 0; ms < 2; ms++) {
                mma_bf16(acc[ms][2*ng],   a_hi[ms], bh[0], bh[2]);
                mma_bf16(acc[ms][2*ng+1], a_hi[ms], bh[1], bh[3]);
            }
#pragma unroll
            for (int ms = 0; ms < 2; ms++) {
                mma_bf16(acc[ms][2*ng],   a_hi[ms], bl[0], bl[2]);
                mma_bf16(acc[ms][2*ng+1], a_hi[ms], bl[1], bl[3]);
            }
#pragma unroll
            for (int ms = 0; ms < 2; ms++) {
                mma_bf16(acc[ms][2*ng],   a_lo[ms], bh[0], bh[2]);
                mma_bf16(acc[ms][2*ng+1], a_lo[ms], bh[1], bh[3]);
            }
        }
    };

    if (STAGES == 2) {
        load_chunk(0, 0); CP_COMMIT();
        for (int c = 0; c < NCH - 1; c++) {
            load_chunk(c + 1, (c + 1) & 1); CP_COMMIT(); CP_WAIT(1);
            __syncthreads();
            compute_chunk(c & 1);
            __syncthreads();
        }
        CP_WAIT(0);
        __syncthreads();
        if (HALFLAST) compute_half0((NCH - 1) & 1);
        else          compute_chunk((NCH - 1) & 1);
    } else {
        load_chunk(0, 0); CP_COMMIT();
        load_chunk(1, 1); CP_COMMIT();
        int bufc = 0;
        for (int c = 0; c < NCH; c++) {
            CP_WAIT(1);
            __syncthreads();
            if (c + 2 < NCH) {
                int b2 = bufc + 2; if (b2 >= 3) b2 -= 3;
                load_chunk(c + 2, b2);
            }
            CP_COMMIT();
            compute_chunk(bufc);
            bufc = (bufc == 2) ? 0 : bufc + 1;
        }
    }

    const int g = lane >> 2, tq = lane & 3;
#pragma unroll
    for (int ms = 0; ms < 2; ms++) {
#pragma unroll
        for (int ns = 0; ns < WNS; ns++) {
            int row = rowBeg + bm * 128 + warpM * 32 + ms * 16 + g;
            int col = bn * BN + warpN * WN + ns * 8 + tq * 2;
#pragma unroll
            for (int half = 0; half < 2; half++) {
                int r = row + half * 8;
                if (r >= rowEnd) continue;
                float v0 = acc[ms][ns][half * 2 + 0];
                float v1 = acc[ms][ns][half * 2 + 1];
                if (FUSE) {
                    if (col >= QD) continue;
                    float2 res;
                    if (col < NODE_D) res = *(const float2*)(nodef + (size_t)r * NODE_D + col);
                    else              res = *(const float2*)(ntime + (size_t)r * TIME_D + (col - NODE_D));
                    float2 bb = *(const float2*)(br + col);
                    v0 += bb.x + res.x;
                    v1 += bb.y + res.y;
                }
                *(float2*)(outp + (size_t)r * OSTR + col) = make_float2(v0, v1);
            }
        }
    }
}

// ---------------- K2: mask-compacted streaming attention (384 threads) --------
__global__ __launch_bounds__(ATH)
void k_attn(const float* __restrict__ nbr_node, const float* __restrict__ nbr_time,
            const float* __restrict__ nbr_edge, const int* __restrict__ masks,
            float* __restrict__ out, int rowBeg)
{
    __shared__ __align__(16) float kv[NN * KD];   // compact slots
    __shared__ __align__(16) float qts[QT];
    __shared__ float sc[NH * NN];                 // scores/attn by neighbor idx
    __shared__ float aw[NH * NN];                 // attn by compact slot

    const int b = rowBeg + blockIdx.x;
    const int t = threadIdx.x;
    const int w = t >> 5, lane = t & 31;
    const uint32_t kvS  = smem_u32(kv);
    const uint32_t qtsS = smem_u32(qts);

    int mv = (lane < NN) ? (masks[(size_t)b * NN + lane] != 0) : 0;
    uint32_t mb = __ballot_sync(0xffffffffu, mv) & 0xFFFFFu;
    const bool allmask = (mb == 0);
    if (allmask) mb = 0xFFFFFu;
    const int nact = __popc(mb);

    for (int i = t; i < QT / 4; i += ATH)
        cp16(qtsS + i * 16, g_qt + (size_t)b * NPAD1 + i * 4, true);
    for (int i = t; i < nact * (NODE_D / 4); i += ATH) {
        int s = i / (NODE_D / 4), j4 = i % (NODE_D / 4);
        int n = __fns(mb, 0, s + 1);
        cp16(kvS + (s * KD + j4 * 4) * 4,
             nbr_node + ((size_t)b * NN + n) * NODE_D + j4 * 4, true);
    }
    for (int i = t; i < nact * (EDGE_D / 4); i += ATH) {
        int s = i / (EDGE_D / 4), j4 = i % (EDGE_D / 4);
        int n = __fns(mb, 0, s + 1);
        cp16(kvS + (s * KD + NODE_D + j4 * 4) * 4,
             nbr_edge + ((size_t)b * NN + n) * EDGE_D + j4 * 4, true);
    }
    for (int i = t; i < nact * (TIME_D / 4); i += ATH) {
        int s = i / (TIME_D / 4), j4 = i % (TIME_D / 4);
        int n = __fns(mb, 0, s + 1);
        cp16(kvS + (s * KD + NODE_D + EDGE_D + j4 * 4) * 4,
             nbr_time + ((size_t)b * NN + n) * TIME_D + j4 * 4, true);
    }
    if (t < NH * NN) sc[t] = -1e10f;
    CP_COMMIT();
    CP_WAIT(0);
    __syncthreads();

    // ---- scores: warp w -> slots w and w+12, both heads ----
#pragma unroll
    for (int rep = 0; rep < 2; rep++) {
        int s = w + rep * 12;
        if (s < nact) {
            int n = __fns(mb, 0, s + 1);
            float a0 = 0.f, a1 = 0.f;
            for (int j = lane; j < KD; j += 32) {
                float kvv = kv[s * KD + j];
                a0 += qts[j] * kvv;
                a1 += qts[KD + j] * kvv;
            }
#pragma unroll
            for (int o = 16; o; o >>= 1) {
                a0 += __shfl_xor_sync(0xffffffffu, a0, o);
                a1 += __shfl_xor_sync(0xffffffffu, a1, o);
            }
            if (lane == 0) {
                sc[n]      = allmask ? 0.f : a0 * ATTN_SCALE;
                sc[NN + n] = allmask ? 0.f : a1 * ATTN_SCALE;
            }
        }
    }
    __syncthreads();

    // ---- softmax ----
    if (w < NH) {
        const int h = w;
        float x = (lane < NN) ? sc[h * NN + lane] : -INFINITY;
        float m = x;
#pragma unroll
        for (int o = 16; o; o >>= 1) m = fmaxf(m, __shfl_xor_sync(0xffffffffu, m, o));
        float e = (lane < NN) ? __expf(x - m) : 0.f;
        float ssum = e;
#pragma unroll
        for (int o = 16; o; o >>= 1) ssum += __shfl_xor_sync(0xffffffffu, ssum, o);
        float a = e / ssum;
        if (lane < NN) {
            out[(size_t)BB * QD + ((size_t)b * NH + h) * NN + lane] = a;
            if ((mb >> lane) & 1u) {
                int s = __popc(mb & ((1u << lane) - 1u));
                aw[h * NN + s] = a;
            }
        }
    }
    __syncthreads();

    // ---- ctx ----
    for (int j = t; j < KD; j += ATH) {
        float c0 = 0.f, c1 = 0.f;
        for (int s = 0; s < nact; ++s) {
            float kvv = kv[s * KD + j];
            c0 += aw[s] * kvv;
            c1 += aw[NN + s] * kvv;
        }
        __nv_bfloat16 h0 = __float2bfloat16(c0);
        __nv_bfloat16 h1 = __float2bfloat16(c1);
        size_t base = (size_t)b * KPAD2;
        g_cxh[base + j]      = h0;
        g_cxl[base + j]      = __float2bfloat16(c0 - __bfloat162float(h0));
        g_cxh[base + KD + j] = h1;
        g_cxl[base + KD + j] = __float2bfloat16(c1 - __bfloat162float(h1));
    }
    if (t < KPAD2 - QT) {
        g_cxh[(size_t)b * KPAD2 + QT + t] = __float2bfloat16(0.f);
        g_cxl[(size_t)b * KPAD2 + QT + t] = __float2bfloat16(0.f);
    }
}

// ---------------- LayerNorm, one warp per row, float4-vectorized ---------------
__global__ __launch_bounds__(256)
void k_ln(const float* __restrict__ gamma, const float* __restrict__ beta,
          float* __restrict__ out)
{
    int gw   = (blockIdx.x * blockDim.x + threadIdx.x) >> 5;
    int lane = threadIdx.x & 31;
    if (gw >= BB) return;
    const float4* x4 = (const float4*)(g_x + (size_t)gw * QD);
    float s = 0.f, s2 = 0.f;
    for (int j = lane; j < QD / 4; j += 32) {
        float4 v = x4[j];
        s  += v.x + v.y + v.z + v.w;
        s2 += v.x * v.x + v.y * v.y + v.z * v.z + v.w * v.w;
    }
#pragma unroll
    for (int o = 16; o; o >>= 1) {
        s  += __shfl_xor_sync(0xffffffffu, s,  o);
        s2 += __shfl_xor_sync(0xffffffffu, s2, o);
    }
    float mu   = s * (1.f / QD);
    float var  = s2 * (1.f / QD) - mu * mu;
    float rstd = rsqrtf(var + LN_EPS);
    float4* o4 = (float4*)(out + (size_t)gw * QD);
    const float4* g4 = (const float4*)gamma;
    const float4* b4 = (const float4*)beta;
    for (int j = lane; j < QD / 4; j += 32) {
        float4 v = x4[j], gg = g4[j], bb = b4[j];
        v.x = (v.x - mu) * rstd * gg.x + bb.x;
        v.y = (v.y - mu) * rstd * gg.y + bb.y;
        v.z = (v.z - mu) * rstd * gg.z + bb.z;
        v.w = (v.w - mu) * rstd * gg.w + bb.w;
        o4[j] = v;
    }
}

// ---------------- side stream for overlap (created once, outside capture) -----
struct SideRes {
    cudaStream_t s2;
    cudaEvent_t eA0, eG0;
    SideRes() {
        cudaStreamCreateWithFlags(&s2, cudaStreamNonBlocking);
        cudaEventCreateWithFlags(&eA0, cudaEventDisableTiming);
        cudaEventCreateWithFlags(&eG0, cudaEventDisableTiming);
    }
};
static SideRes g_side;

// ---------------- launch ------------------------------------------------------
#define SMEM1 (2 * (4 * 128 * 2 * RSTR))                       // 81920 (2-stage, BN=128)
#define SMEM2 (3 * (2 * 128 * 2 * RSTR + 2 * 96 * 2 * RSTR))   // 107520 (3-stage, BN=96)

extern "C" void kernel_launch(void* const* d_in, const int* in_sizes, int n_in,
                              void* d_out, int out_size)
{
    const float* nodef    = (const float*)d_in[0];
    const float* ntime    = (const float*)d_in[1];
    const float* nbr_node = (const float*)d_in[2];
    const float* nbr_time = (const float*)d_in[3];
    const float* nbr_edge = (const float*)d_in[4];
    const int*   masks    = (const int*)  d_in[5];
    const float* Wq       = (const float*)d_in[6];
    const float* Wk       = (const float*)d_in[7];
    const float* Wv       = (const float*)d_in[8];
    const float* Wr       = (const float*)d_in[9];
    const float* br       = (const float*)d_in[10];
    const float* gamma    = (const float*)d_in[11];
    const float* beta     = (const float*)d_in[12];
    float* out = (float*)d_out;

    auto g1 = k_gemm_mma<128, NCHUNK1, KPAD1, NPAD1, false, 1, 2, true>;
    auto g2 = k_gemm_mma<96,  NCHUNK2, KPAD2, QD,    true,  2, 3, false>;
    cudaFuncSetAttribute(g1, cudaFuncAttributeMaxDynamicSharedMemorySize, SMEM1);
    cudaFuncSetAttribute(g2, cudaFuncAttributeMaxDynamicSharedMemorySize, SMEM2);

    k_prelude<<<NB_PREP + NB_FM + NB_RV, 256>>>(nodef, ntime, Wq, Wk, Wr, Wv);

    dim3 grid1((BB + 127) / 128, NPAD1 / 128);
    g1<<<grid1, 256, SMEM1>>>(nodef, ntime, br, 0, BB);

    // attn first half on main; record event
    k_attn<<<RSPLIT, ATH>>>(nbr_node, nbr_time, nbr_edge, masks, out, 0);
    cudaEventRecord(g_side.eA0, 0);

    // G2 first half on side stream (overlaps attn second half)
    cudaStreamWaitEvent(g_side.s2, g_side.eA0, 0);
    dim3 grid2a(TSPLIT, NPAD2 / 96);
    g2<<<grid2a, 256, SMEM2, g_side.s2>>>(nodef, ntime, br, 0, RSPLIT);
    cudaEventRecord(g_side.eG0, g_side.s2);

    // attn second half on main (concurrent with G2 first half)
    k_attn<<<BB - RSPLIT, ATH>>>(nbr_node, nbr_time, nbr_edge, masks, out, RSPLIT);

    // G2 second half on main
    dim3 grid2b(NTILES2 - TSPLIT, NPAD2 / 96);
    g2<<<grid2b, 256, SMEM2>>>(nodef, ntime, br, RSPLIT, BB);

    // join: LN waits for both G2 halves
    cudaStreamWaitEvent(0, g_side.eG0, 0);
    k_ln<<<(BB * 32 + 255) / 256, 256>>>(gamma, beta, out);
}